// round 1
// baseline (speedup 1.0000x reference)
#include <cuda_runtime.h>
#include <math.h>

namespace {

constexpr int T_TOK = 8192;   // B*S = 4*2048
constexpr int DIM   = 512;
constexpr int FDIM  = 2048;
constexpr int NEXP  = 8;
constexpr int MAXB  = 8192;   // max rows per expert bucket (= T, power of 2)
constexpr int NROWS = 2 * T_TOK;  // total assignments (top-2)

// ---- device scratch (static: no allocations allowed) ----
__device__ int   g_count[NEXP];
__device__ int   g_offset[NEXP];
__device__ float g_probsum[NEXP];
__device__ int   g_tok[NEXP * MAXB];
__device__ int   g_slot[T_TOK * 2];     // e*MAXB + pos per (token, k)
__device__ float g_slotw[T_TOK * 2];    // normalized router weight
__device__ float g_hidden[(size_t)NROWS * FDIM];  // 128 MB
__device__ float g_oscr[(size_t)NROWS * DIM];     // 32 MB

__global__ void init_k() {
    if (threadIdx.x < NEXP) { g_count[threadIdx.x] = 0; g_probsum[threadIdx.x] = 0.f; }
}

// One warp per token: logits -> softmax -> top-2 -> bucket append.
__global__ void router_k(const float* __restrict__ x, const float* __restrict__ gw) {
    __shared__ float s_gw[DIM * NEXP];
    for (int i = threadIdx.x; i < DIM * NEXP; i += blockDim.x) s_gw[i] = gw[i];
    __syncthreads();

    int t    = (int)((blockIdx.x * blockDim.x + threadIdx.x) >> 5);
    int lane = threadIdx.x & 31;
    if (t >= T_TOK) return;

    const float* xr = x + (size_t)t * DIM;
    float acc[NEXP];
#pragma unroll
    for (int e = 0; e < NEXP; e++) acc[e] = 0.f;
    for (int d = lane; d < DIM; d += 32) {
        float xv = xr[d];
#pragma unroll
        for (int e = 0; e < NEXP; e++) acc[e] = fmaf(xv, s_gw[d * NEXP + e], acc[e]);
    }
#pragma unroll
    for (int off = 16; off; off >>= 1) {
#pragma unroll
        for (int e = 0; e < NEXP; e++)
            acc[e] += __shfl_xor_sync(0xffffffffu, acc[e], off);
    }
    if (lane != 0) return;

    float mx = acc[0];
#pragma unroll
    for (int e = 1; e < NEXP; e++) mx = fmaxf(mx, acc[e]);
    float p[NEXP]; float s = 0.f;
#pragma unroll
    for (int e = 0; e < NEXP; e++) { p[e] = expf(acc[e] - mx); s += p[e]; }
    float inv = 1.f / s;
#pragma unroll
    for (int e = 0; e < NEXP; e++) { p[e] *= inv; atomicAdd(&g_probsum[e], p[e]); }

    // top-2 (lowest index wins ties, matching jax.lax.top_k)
    int i0 = 0;
#pragma unroll
    for (int e = 1; e < NEXP; e++) if (p[e] > p[i0]) i0 = e;
    int i1 = (i0 == 0) ? 1 : 0;
#pragma unroll
    for (int e = 0; e < NEXP; e++) if (e != i0 && p[e] > p[i1]) i1 = e;

    float w0 = p[i0], w1 = p[i1];
    float ws = 1.f / (w0 + w1);
    w0 *= ws; w1 *= ws;

    int p0 = atomicAdd(&g_count[i0], 1);
    g_tok[i0 * MAXB + p0] = t;
    g_slot[t * 2 + 0]  = i0 * MAXB + p0;
    g_slotw[t * 2 + 0] = w0;
    int p1 = atomicAdd(&g_count[i1], 1);
    g_tok[i1 * MAXB + p1] = t;
    g_slot[t * 2 + 1]  = i1 * MAXB + p1;
    g_slotw[t * 2 + 1] = w1;
}

__global__ void finalize_k(float* __restrict__ loss_out) {
    int off = 0;
    for (int e = 0; e < NEXP; e++) { g_offset[e] = off; off += g_count[e]; }
    float s = 0.f;
    for (int e = 0; e < NEXP; e++) {
        float m = g_probsum[e] * (1.f / (float)T_TOK);
        s += m * m;
    }
    *loss_out = (float)NEXP * s;
}

// GEMM1: hidden = gelu(x[gathered rows] @ w1[e] + b1[e]).  64x64 tile, BK=32.
__global__ __launch_bounds__(256) void ffn1_k(const float* __restrict__ x,
                                              const float* __restrict__ w1,
                                              const float* __restrict__ b1) {
    const int e  = blockIdx.z;
    const int ne = g_count[e];
    const int m0 = blockIdx.x * 64;
    if (m0 >= ne) return;
    const int n0   = blockIdx.y * 64;
    const int base = g_offset[e];

    __shared__ float As[64][36];   // padded, row-major (M x K)
    __shared__ float Bs[32][64];   // K x N

    const int tid = threadIdx.x;
    const int tx  = tid & 15;      // N group
    const int ty  = tid >> 4;      // M group

    float acc[4][4];
#pragma unroll
    for (int i = 0; i < 4; i++)
#pragma unroll
        for (int j = 0; j < 4; j++) acc[i][j] = 0.f;

    const float* Wb = w1 + (size_t)e * DIM * FDIM + n0;

    for (int k0 = 0; k0 < DIM; k0 += 32) {
#pragma unroll
        for (int l = 0; l < 2; l++) {
            int idx = tid + l * 256;             // 0..511
            int row = idx >> 3;                  // 0..63
            int kq  = idx & 7;
            int mrow = m0 + row;
            int tok  = g_tok[e * MAXB + min(mrow, ne - 1)];
            float4 v = *(const float4*)(x + (size_t)tok * DIM + k0 + kq * 4);
            *(float4*)&As[row][kq * 4] = v;
        }
#pragma unroll
        for (int l = 0; l < 2; l++) {
            int idx = tid + l * 256;
            int kr = idx >> 4;                   // 0..31
            int nq = idx & 15;
            float4 v = *(const float4*)(Wb + (size_t)(k0 + kr) * FDIM + nq * 4);
            *(float4*)&Bs[kr][nq * 4] = v;
        }
        __syncthreads();
#pragma unroll
        for (int kk = 0; kk < 32; kk++) {
            float a0 = As[ty * 4 + 0][kk];
            float a1 = As[ty * 4 + 1][kk];
            float a2 = As[ty * 4 + 2][kk];
            float a3 = As[ty * 4 + 3][kk];
            float4 b = *(const float4*)&Bs[kk][tx * 4];
            acc[0][0] = fmaf(a0, b.x, acc[0][0]); acc[0][1] = fmaf(a0, b.y, acc[0][1]);
            acc[0][2] = fmaf(a0, b.z, acc[0][2]); acc[0][3] = fmaf(a0, b.w, acc[0][3]);
            acc[1][0] = fmaf(a1, b.x, acc[1][0]); acc[1][1] = fmaf(a1, b.y, acc[1][1]);
            acc[1][2] = fmaf(a1, b.z, acc[1][2]); acc[1][3] = fmaf(a1, b.w, acc[1][3]);
            acc[2][0] = fmaf(a2, b.x, acc[2][0]); acc[2][1] = fmaf(a2, b.y, acc[2][1]);
            acc[2][2] = fmaf(a2, b.z, acc[2][2]); acc[2][3] = fmaf(a2, b.w, acc[2][3]);
            acc[3][0] = fmaf(a3, b.x, acc[3][0]); acc[3][1] = fmaf(a3, b.y, acc[3][1]);
            acc[3][2] = fmaf(a3, b.z, acc[3][2]); acc[3][3] = fmaf(a3, b.w, acc[3][3]);
        }
        __syncthreads();
    }
#pragma unroll
    for (int i = 0; i < 4; i++) {
        int mrow = m0 + ty * 4 + i;
        if (mrow < ne) {
            float4 bb = *(const float4*)(b1 + (size_t)e * FDIM + n0 + tx * 4);
            float4 o;
            float c0 = acc[i][0] + bb.x; o.x = c0 * normcdff(c0);
            float c1 = acc[i][1] + bb.y; o.y = c1 * normcdff(c1);
            float c2 = acc[i][2] + bb.z; o.z = c2 * normcdff(c2);
            float c3 = acc[i][3] + bb.w; o.w = c3 * normcdff(c3);
            *(float4*)(g_hidden + (size_t)(base + mrow) * FDIM + n0 + tx * 4) = o;
        }
    }
}

// GEMM2: out = hidden @ w2[e] + b2[e]
__global__ __launch_bounds__(256) void ffn2_k(const float* __restrict__ w2,
                                              const float* __restrict__ b2) {
    const int e  = blockIdx.z;
    const int ne = g_count[e];
    const int m0 = blockIdx.x * 64;
    if (m0 >= ne) return;
    const int n0   = blockIdx.y * 64;
    const int base = g_offset[e];

    __shared__ float As[64][36];
    __shared__ float Bs[32][64];

    const int tid = threadIdx.x;
    const int tx  = tid & 15;
    const int ty  = tid >> 4;

    float acc[4][4];
#pragma unroll
    for (int i = 0; i < 4; i++)
#pragma unroll
        for (int j = 0; j < 4; j++) acc[i][j] = 0.f;

    const float* Wb = w2 + (size_t)e * FDIM * DIM + n0;

    for (int k0 = 0; k0 < FDIM; k0 += 32) {
#pragma unroll
        for (int l = 0; l < 2; l++) {
            int idx = tid + l * 256;
            int row = idx >> 3;
            int kq  = idx & 7;
            int r   = base + min(m0 + row, ne - 1);
            float4 v = *(const float4*)(g_hidden + (size_t)r * FDIM + k0 + kq * 4);
            *(float4*)&As[row][kq * 4] = v;
        }
#pragma unroll
        for (int l = 0; l < 2; l++) {
            int idx = tid + l * 256;
            int kr = idx >> 4;
            int nq = idx & 15;
            float4 v = *(const float4*)(Wb + (size_t)(k0 + kr) * DIM + nq * 4);
            *(float4*)&Bs[kr][nq * 4] = v;
        }
        __syncthreads();
#pragma unroll
        for (int kk = 0; kk < 32; kk++) {
            float a0 = As[ty * 4 + 0][kk];
            float a1 = As[ty * 4 + 1][kk];
            float a2 = As[ty * 4 + 2][kk];
            float a3 = As[ty * 4 + 3][kk];
            float4 b = *(const float4*)&Bs[kk][tx * 4];
            acc[0][0] = fmaf(a0, b.x, acc[0][0]); acc[0][1] = fmaf(a0, b.y, acc[0][1]);
            acc[0][2] = fmaf(a0, b.z, acc[0][2]); acc[0][3] = fmaf(a0, b.w, acc[0][3]);
            acc[1][0] = fmaf(a1, b.x, acc[1][0]); acc[1][1] = fmaf(a1, b.y, acc[1][1]);
            acc[1][2] = fmaf(a1, b.z, acc[1][2]); acc[1][3] = fmaf(a1, b.w, acc[1][3]);
            acc[2][0] = fmaf(a2, b.x, acc[2][0]); acc[2][1] = fmaf(a2, b.y, acc[2][1]);
            acc[2][2] = fmaf(a2, b.z, acc[2][2]); acc[2][3] = fmaf(a2, b.w, acc[2][3]);
            acc[3][0] = fmaf(a3, b.x, acc[3][0]); acc[3][1] = fmaf(a3, b.y, acc[3][1]);
            acc[3][2] = fmaf(a3, b.z, acc[3][2]); acc[3][3] = fmaf(a3, b.w, acc[3][3]);
        }
        __syncthreads();
    }
#pragma unroll
    for (int i = 0; i < 4; i++) {
        int mrow = m0 + ty * 4 + i;
        if (mrow < ne) {
            float4 bb = *(const float4*)(b2 + (size_t)e * DIM + n0 + tx * 4);
            float4 o;
            o.x = acc[i][0] + bb.x;
            o.y = acc[i][1] + bb.y;
            o.z = acc[i][2] + bb.z;
            o.w = acc[i][3] + bb.w;
            *(float4*)(g_oscr + (size_t)(base + mrow) * DIM + n0 + tx * 4) = o;
        }
    }
}

// y[t] = w0 * out[row(t,0)] + w1 * out[row(t,1)]  (deterministic, no atomics)
__global__ void combine_k(float* __restrict__ y) {
    int gid = blockIdx.x * blockDim.x + threadIdx.x;  // T_TOK * DIM/4
    if (gid >= T_TOK * (DIM / 4)) return;
    int t = gid >> 7;             // / (DIM/4) = /128
    int q = (gid & 127) * 4;
    int s0 = g_slot[t * 2 + 0], s1 = g_slot[t * 2 + 1];
    float w0 = g_slotw[t * 2 + 0], w1 = g_slotw[t * 2 + 1];
    int r0 = g_offset[s0 >> 13] + (s0 & (MAXB - 1));
    int r1 = g_offset[s1 >> 13] + (s1 & (MAXB - 1));
    float4 a = *(const float4*)(g_oscr + (size_t)r0 * DIM + q);
    float4 b = *(const float4*)(g_oscr + (size_t)r1 * DIM + q);
    float4 o;
    o.x = w0 * a.x + w1 * b.x;
    o.y = w0 * a.y + w1 * b.y;
    o.z = w0 * a.z + w1 * b.z;
    o.w = w0 * a.w + w1 * b.w;
    *(float4*)(y + (size_t)t * DIM + q) = o;
}

}  // namespace

extern "C" void kernel_launch(void* const* d_in, const int* in_sizes, int n_in,
                              void* d_out, int out_size) {
    const float* x  = (const float*)d_in[0];
    const float* gw = (const float*)d_in[1];
    const float* w1 = (const float*)d_in[2];
    const float* b1 = (const float*)d_in[3];
    const float* w2 = (const float*)d_in[4];
    const float* b2 = (const float*)d_in[5];
    float* y    = (float*)d_out;
    float* loss = y + (out_size - 1);   // output layout: [y (T*D), loss]

    init_k<<<1, 32>>>();
    router_k<<<(T_TOK * 32 + 255) / 256, 256>>>(x, gw);
    finalize_k<<<1, 1>>>(loss);
    ffn1_k<<<dim3(T_TOK / 64, FDIM / 64, NEXP), 256>>>(x, w1, b1);
    ffn2_k<<<dim3(T_TOK / 64, DIM / 64, NEXP), 256>>>(w2, b2);
    combine_k<<<(T_TOK * (DIM / 4) + 255) / 256, 256>>>(y);
}

// round 2
// speedup vs baseline: 2.8508x; 2.8508x over previous
#include <cuda_runtime.h>
#include <math.h>
#include <stdint.h>

namespace {

constexpr int T_TOK = 8192;   // B*S
constexpr int DIM   = 512;
constexpr int FDIM  = 2048;
constexpr int NEXP  = 8;
constexpr int MAXB  = 8192;
constexpr int NROWS = 2 * T_TOK;

// GEMM tiling
constexpr int BM = 128, BN = 128, BK = 32;
constexpr int ASTRIDE = 36;    // 128 rows x 36 floats (16B-aligned pad, conflict-free)
constexpr int BSTRIDE = 136;   // 32 rows x 136 floats
constexpr int A_ELEMS = BM * ASTRIDE;          // 4608
constexpr int B_ELEMS = BK * BSTRIDE;          // 4352
constexpr int STAGE_ELEMS = A_ELEMS + B_ELEMS; // 8960 floats
constexpr int SMEM_BYTES = 2 * STAGE_ELEMS * 4; // 71680 B

// ---- device scratch ----
__device__ int   g_count[NEXP];
__device__ int   g_offset[NEXP];
__device__ float g_probsum[NEXP];
__device__ int   g_tok[NEXP * MAXB];
__device__ int   g_slot[T_TOK * 2];
__device__ float g_slotw[T_TOK * 2];
__device__ float g_hidden[(size_t)NROWS * FDIM];
__device__ float g_oscr[(size_t)NROWS * DIM];

__global__ void init_k() {
    if (threadIdx.x < NEXP) { g_count[threadIdx.x] = 0; g_probsum[threadIdx.x] = 0.f; }
}

__global__ void router_k(const float* __restrict__ x, const float* __restrict__ gw) {
    __shared__ float s_gw[DIM * NEXP];
    for (int i = threadIdx.x; i < DIM * NEXP; i += blockDim.x) s_gw[i] = gw[i];
    __syncthreads();

    int t    = (int)((blockIdx.x * blockDim.x + threadIdx.x) >> 5);
    int lane = threadIdx.x & 31;
    if (t >= T_TOK) return;

    const float* xr = x + (size_t)t * DIM;
    float acc[NEXP];
#pragma unroll
    for (int e = 0; e < NEXP; e++) acc[e] = 0.f;
    for (int d = lane; d < DIM; d += 32) {
        float xv = xr[d];
#pragma unroll
        for (int e = 0; e < NEXP; e++) acc[e] = fmaf(xv, s_gw[d * NEXP + e], acc[e]);
    }
#pragma unroll
    for (int off = 16; off; off >>= 1) {
#pragma unroll
        for (int e = 0; e < NEXP; e++)
            acc[e] += __shfl_xor_sync(0xffffffffu, acc[e], off);
    }
    if (lane != 0) return;

    float mx = acc[0];
#pragma unroll
    for (int e = 1; e < NEXP; e++) mx = fmaxf(mx, acc[e]);
    float p[NEXP]; float s = 0.f;
#pragma unroll
    for (int e = 0; e < NEXP; e++) { p[e] = expf(acc[e] - mx); s += p[e]; }
    float inv = 1.f / s;
#pragma unroll
    for (int e = 0; e < NEXP; e++) { p[e] *= inv; atomicAdd(&g_probsum[e], p[e]); }

    int i0 = 0;
#pragma unroll
    for (int e = 1; e < NEXP; e++) if (p[e] > p[i0]) i0 = e;
    int i1 = (i0 == 0) ? 1 : 0;
#pragma unroll
    for (int e = 0; e < NEXP; e++) if (e != i0 && p[e] > p[i1]) i1 = e;

    float w0 = p[i0], w1 = p[i1];
    float ws = 1.f / (w0 + w1);
    w0 *= ws; w1 *= ws;

    int p0 = atomicAdd(&g_count[i0], 1);
    g_tok[i0 * MAXB + p0] = t;
    g_slot[t * 2 + 0]  = i0 * MAXB + p0;
    g_slotw[t * 2 + 0] = w0;
    int p1 = atomicAdd(&g_count[i1], 1);
    g_tok[i1 * MAXB + p1] = t;
    g_slot[t * 2 + 1]  = i1 * MAXB + p1;
    g_slotw[t * 2 + 1] = w1;
}

__global__ void finalize_k(float* __restrict__ loss_out) {
    int off = 0;
    for (int e = 0; e < NEXP; e++) { g_offset[e] = off; off += g_count[e]; }
    float s = 0.f;
    for (int e = 0; e < NEXP; e++) {
        float m = g_probsum[e] * (1.f / (float)T_TOK);
        s += m * m;
    }
    *loss_out = (float)NEXP * s;
}

// ---- helpers ----
__device__ __forceinline__ void cp_async16(uint32_t saddr, const void* gptr) {
    asm volatile("cp.async.cg.shared.global [%0], [%1], 16;\n" :: "r"(saddr), "l"(gptr));
}
__device__ __forceinline__ void cp_commit() {
    asm volatile("cp.async.commit_group;\n" ::: "memory");
}
__device__ __forceinline__ void cp_wait1() {
    asm volatile("cp.async.wait_group 1;\n" ::: "memory");
}
__device__ __forceinline__ uint32_t f2tf32(float f) {
    uint32_t r;
    asm("cvt.rna.tf32.f32 %0, %1;\n" : "=r"(r) : "f"(f));
    return r;
}
__device__ __forceinline__ void mma_tf32(float c[4], uint32_t a0, uint32_t a1,
                                         uint32_t a2, uint32_t a3,
                                         uint32_t b0, uint32_t b1) {
    asm volatile(
        "mma.sync.aligned.m16n8k8.row.col.f32.tf32.tf32.f32 "
        "{%0,%1,%2,%3}, {%4,%5,%6,%7}, {%8,%9}, {%0,%1,%2,%3};\n"
        : "+f"(c[0]), "+f"(c[1]), "+f"(c[2]), "+f"(c[3])
        : "r"(a0), "r"(a1), "r"(a2), "r"(a3), "r"(b0), "r"(b1));
}

// Compute one BK=32 slab: 4 k8-steps, 16 mmas each.
__device__ __forceinline__ void compute_slab(const float* __restrict__ As,
                                             const float* __restrict__ Bs,
                                             int wm, int wn, int lane,
                                             float acc[4][4][4]) {
#pragma unroll
    for (int ks = 0; ks < 4; ks++) {
        uint32_t af[4][4], bf[4][2];
        int c0 = ks * 8 + (lane & 3);
#pragma unroll
        for (int mt = 0; mt < 4; mt++) {
            int r = wm + mt * 16 + (lane >> 2);
            af[mt][0] = f2tf32(As[r * ASTRIDE + c0]);
            af[mt][1] = f2tf32(As[(r + 8) * ASTRIDE + c0]);
            af[mt][2] = f2tf32(As[r * ASTRIDE + c0 + 4]);
            af[mt][3] = f2tf32(As[(r + 8) * ASTRIDE + c0 + 4]);
        }
#pragma unroll
        for (int nt = 0; nt < 4; nt++) {
            int col = wn + nt * 8 + (lane >> 2);
            bf[nt][0] = f2tf32(Bs[c0 * BSTRIDE + col]);
            bf[nt][1] = f2tf32(Bs[(c0 + 4) * BSTRIDE + col]);
        }
#pragma unroll
        for (int mt = 0; mt < 4; mt++)
#pragma unroll
            for (int nt = 0; nt < 4; nt++)
                mma_tf32(acc[mt][nt], af[mt][0], af[mt][1], af[mt][2], af[mt][3],
                         bf[nt][0], bf[nt][1]);
    }
}

// GEMM1: hidden = gelu(gather(x) @ w1[e] + b1[e]).  K=512.
__global__ __launch_bounds__(256, 2) void ffn1_k(const float* __restrict__ x,
                                                 const float* __restrict__ w1,
                                                 const float* __restrict__ b1) {
    const int e  = blockIdx.z;
    const int ne = g_count[e];
    const int m0 = blockIdx.x * BM;
    if (m0 >= ne) return;
    const int n0   = blockIdx.y * BN;
    const int base = g_offset[e];

    extern __shared__ float smem[];
    const int tid  = threadIdx.x;
    const int lane = tid & 31;
    const int warp = tid >> 5;
    const int wm   = (warp & 1) * 64;
    const int wn   = (warp >> 1) * 32;

    // per-thread load slots: A chunks idx = tid + l*256 (row = idx>>3, ch = idx&7)
    const float* srcA[4];
    uint32_t dstA[4];
#pragma unroll
    for (int l = 0; l < 4; l++) {
        int idx = tid + l * 256;
        int row = idx >> 3, ch = idx & 7;
        int tok = g_tok[e * MAXB + min(m0 + row, ne - 1)];
        srcA[l] = x + (size_t)tok * DIM + ch * 4;
        dstA[l] = (uint32_t)(row * ASTRIDE + ch * 4) * 4u;
    }
    const float* srcB[4];
    uint32_t dstB[4];
    const float* Wb = w1 + (size_t)e * DIM * FDIM + n0;
#pragma unroll
    for (int l = 0; l < 4; l++) {
        int idx = tid + l * 256;
        int kr = idx >> 5, ch = idx & 31;
        srcB[l] = Wb + (size_t)kr * FDIM + ch * 4;
        dstB[l] = (uint32_t)(A_ELEMS + kr * BSTRIDE + ch * 4) * 4u;
    }
    uint32_t sbase = (uint32_t)__cvta_generic_to_shared(smem);

    auto load_stage = [&](int s, int k0) {
        uint32_t soff = sbase + (uint32_t)(s * STAGE_ELEMS * 4);
#pragma unroll
        for (int l = 0; l < 4; l++) cp_async16(soff + dstA[l], srcA[l] + k0);
#pragma unroll
        for (int l = 0; l < 4; l++) cp_async16(soff + dstB[l], srcB[l] + (size_t)k0 * FDIM);
    };

    float acc[4][4][4];
#pragma unroll
    for (int i = 0; i < 4; i++)
#pragma unroll
        for (int j = 0; j < 4; j++)
#pragma unroll
            for (int k = 0; k < 4; k++) acc[i][j][k] = 0.f;

    constexpr int KITERS = DIM / BK;  // 16
    load_stage(0, 0);
    cp_commit();
    for (int it = 0; it < KITERS; it++) {
        if (it + 1 < KITERS) load_stage((it + 1) & 1, (it + 1) * BK);
        cp_commit();
        cp_wait1();
        __syncthreads();
        const float* As = smem + (it & 1) * STAGE_ELEMS;
        compute_slab(As, As + A_ELEMS, wm, wn, lane, acc);
        __syncthreads();
    }

    // epilogue: bias + exact gelu, store to g_hidden
#pragma unroll
    for (int nt = 0; nt < 4; nt++) {
        int c = n0 + wn + nt * 8 + 2 * (lane & 3);
        float2 bb = *(const float2*)(b1 + (size_t)e * FDIM + c);
#pragma unroll
        for (int mt = 0; mt < 4; mt++) {
            int r = wm + mt * 16 + (lane >> 2);
            int mrow0 = m0 + r, mrow1 = mrow0 + 8;
            if (mrow0 < ne) {
                float v0 = acc[mt][nt][0] + bb.x;
                float v1 = acc[mt][nt][1] + bb.y;
                float2 o = { v0 * normcdff(v0), v1 * normcdff(v1) };
                *(float2*)(g_hidden + (size_t)(base + mrow0) * FDIM + c) = o;
            }
            if (mrow1 < ne) {
                float v2 = acc[mt][nt][2] + bb.x;
                float v3 = acc[mt][nt][3] + bb.y;
                float2 o = { v2 * normcdff(v2), v3 * normcdff(v3) };
                *(float2*)(g_hidden + (size_t)(base + mrow1) * FDIM + c) = o;
            }
        }
    }
}

// GEMM2: out = hidden @ w2[e] + b2[e].  K=2048, N=512.
__global__ __launch_bounds__(256, 2) void ffn2_k(const float* __restrict__ w2,
                                                 const float* __restrict__ b2) {
    const int e  = blockIdx.z;
    const int ne = g_count[e];
    const int m0 = blockIdx.x * BM;
    if (m0 >= ne) return;
    const int n0   = blockIdx.y * BN;
    const int base = g_offset[e];

    extern __shared__ float smem[];
    const int tid  = threadIdx.x;
    const int lane = tid & 31;
    const int warp = tid >> 5;
    const int wm   = (warp & 1) * 64;
    const int wn   = (warp >> 1) * 32;

    const float* srcA[4];
    uint32_t dstA[4];
#pragma unroll
    for (int l = 0; l < 4; l++) {
        int idx = tid + l * 256;
        int row = idx >> 3, ch = idx & 7;
        int r = base + min(m0 + row, ne - 1);
        srcA[l] = g_hidden + (size_t)r * FDIM + ch * 4;
        dstA[l] = (uint32_t)(row * ASTRIDE + ch * 4) * 4u;
    }
    const float* srcB[4];
    uint32_t dstB[4];
    const float* Wb = w2 + (size_t)e * FDIM * DIM + n0;
#pragma unroll
    for (int l = 0; l < 4; l++) {
        int idx = tid + l * 256;
        int kr = idx >> 5, ch = idx & 31;
        srcB[l] = Wb + (size_t)kr * DIM + ch * 4;
        dstB[l] = (uint32_t)(A_ELEMS + kr * BSTRIDE + ch * 4) * 4u;
    }
    uint32_t sbase = (uint32_t)__cvta_generic_to_shared(smem);

    auto load_stage = [&](int s, int k0) {
        uint32_t soff = sbase + (uint32_t)(s * STAGE_ELEMS * 4);
#pragma unroll
        for (int l = 0; l < 4; l++) cp_async16(soff + dstA[l], srcA[l] + k0);
#pragma unroll
        for (int l = 0; l < 4; l++) cp_async16(soff + dstB[l], srcB[l] + (size_t)k0 * DIM);
    };

    float acc[4][4][4];
#pragma unroll
    for (int i = 0; i < 4; i++)
#pragma unroll
        for (int j = 0; j < 4; j++)
#pragma unroll
            for (int k = 0; k < 4; k++) acc[i][j][k] = 0.f;

    constexpr int KITERS = FDIM / BK;  // 64
    load_stage(0, 0);
    cp_commit();
    for (int it = 0; it < KITERS; it++) {
        if (it + 1 < KITERS) load_stage((it + 1) & 1, (it + 1) * BK);
        cp_commit();
        cp_wait1();
        __syncthreads();
        const float* As = smem + (it & 1) * STAGE_ELEMS;
        compute_slab(As, As + A_ELEMS, wm, wn, lane, acc);
        __syncthreads();
    }

#pragma unroll
    for (int nt = 0; nt < 4; nt++) {
        int c = n0 + wn + nt * 8 + 2 * (lane & 3);
        float2 bb = *(const float2*)(b2 + (size_t)e * DIM + c);
#pragma unroll
        for (int mt = 0; mt < 4; mt++) {
            int r = wm + mt * 16 + (lane >> 2);
            int mrow0 = m0 + r, mrow1 = mrow0 + 8;
            if (mrow0 < ne) {
                float2 o = { acc[mt][nt][0] + bb.x, acc[mt][nt][1] + bb.y };
                *(float2*)(g_oscr + (size_t)(base + mrow0) * DIM + c) = o;
            }
            if (mrow1 < ne) {
                float2 o = { acc[mt][nt][2] + bb.x, acc[mt][nt][3] + bb.y };
                *(float2*)(g_oscr + (size_t)(base + mrow1) * DIM + c) = o;
            }
        }
    }
}

__global__ void combine_k(float* __restrict__ y) {
    int gid = blockIdx.x * blockDim.x + threadIdx.x;
    if (gid >= T_TOK * (DIM / 4)) return;
    int t = gid >> 7;
    int q = (gid & 127) * 4;
    int s0 = g_slot[t * 2 + 0], s1 = g_slot[t * 2 + 1];
    float w0 = g_slotw[t * 2 + 0], w1 = g_slotw[t * 2 + 1];
    int r0 = g_offset[s0 >> 13] + (s0 & (MAXB - 1));
    int r1 = g_offset[s1 >> 13] + (s1 & (MAXB - 1));
    float4 a = *(const float4*)(g_oscr + (size_t)r0 * DIM + q);
    float4 b = *(const float4*)(g_oscr + (size_t)r1 * DIM + q);
    float4 o;
    o.x = w0 * a.x + w1 * b.x;
    o.y = w0 * a.y + w1 * b.y;
    o.z = w0 * a.z + w1 * b.z;
    o.w = w0 * a.w + w1 * b.w;
    *(float4*)(y + (size_t)t * DIM + q) = o;
}

}  // namespace

extern "C" void kernel_launch(void* const* d_in, const int* in_sizes, int n_in,
                              void* d_out, int out_size) {
    const float* x  = (const float*)d_in[0];
    const float* gw = (const float*)d_in[1];
    const float* w1 = (const float*)d_in[2];
    const float* b1 = (const float*)d_in[3];
    const float* w2 = (const float*)d_in[4];
    const float* b2 = (const float*)d_in[5];
    float* y    = (float*)d_out;
    float* loss = y + (out_size - 1);

    static bool attr_done = false;
    if (!attr_done) {
        cudaFuncSetAttribute(ffn1_k, cudaFuncAttributeMaxDynamicSharedMemorySize, SMEM_BYTES);
        cudaFuncSetAttribute(ffn2_k, cudaFuncAttributeMaxDynamicSharedMemorySize, SMEM_BYTES);
        attr_done = true;
    }

    init_k<<<1, 32>>>();
    router_k<<<(T_TOK * 32 + 255) / 256, 256>>>(x, gw);
    finalize_k<<<1, 1>>>(loss);
    ffn1_k<<<dim3(T_TOK / BM, FDIM / BN, NEXP), 256, SMEM_BYTES>>>(x, w1, b1);
    ffn2_k<<<dim3(T_TOK / BM, DIM / BN, NEXP), 256, SMEM_BYTES>>>(w2, b2);
    combine_k<<<(T_TOK * (DIM / 4) + 255) / 256, 256>>>(y);
}

// round 3
// speedup vs baseline: 2.8728x; 1.0077x over previous
#include <cuda_runtime.h>
#include <math.h>
#include <stdint.h>

namespace {

constexpr int T_TOK = 8192;   // B*S
constexpr int DIM   = 512;
constexpr int FDIM  = 2048;
constexpr int NEXP  = 8;
constexpr int MAXB  = 8192;
constexpr int NROWS = 2 * T_TOK;

// GEMM tiling
constexpr int BM = 128, BN = 128, BK = 32;
constexpr int ASTRIDE = 36;
constexpr int BSTRIDE = 136;
constexpr int A_ELEMS = BM * ASTRIDE;          // 4608
constexpr int B_ELEMS = BK * BSTRIDE;          // 4352
constexpr int STAGE_ELEMS = A_ELEMS + B_ELEMS; // 8960 floats
constexpr int SMEM_BYTES = 2 * STAGE_ELEMS * 4;

// ---- device scratch ----
__device__ int   g_count[NEXP];
__device__ int   g_offset[NEXP];
__device__ float g_probsum[NEXP];
__device__ int   g_tok[NEXP * MAXB];
__device__ int   g_slot[T_TOK * 2];
__device__ float g_slotw[T_TOK * 2];
__device__ float g_hidden[(size_t)NROWS * FDIM];        // tf32-rounded
__device__ float g_oscr[(size_t)NROWS * DIM];
__device__ float g_xr[(size_t)T_TOK * DIM];             // tf32-rounded x
__device__ float g_w1r[(size_t)NEXP * DIM * FDIM];      // tf32-rounded w1
__device__ float g_w2r[(size_t)NEXP * FDIM * DIM];      // tf32-rounded w2

__device__ __forceinline__ uint32_t f2tf32(float f) {
    uint32_t r;
    asm("cvt.rna.tf32.f32 %0, %1;\n" : "=r"(r) : "f"(f));
    return r;
}

__global__ void init_k() {
    if (threadIdx.x < NEXP) { g_count[threadIdx.x] = 0; g_probsum[threadIdx.x] = 0.f; }
}

// elementwise tf32 pre-round (float4 vectorized)
__global__ void round_k(const float* __restrict__ src, float* __restrict__ dst, int n4) {
    int i = blockIdx.x * blockDim.x + threadIdx.x;
    if (i >= n4) return;
    float4 v = ((const float4*)src)[i];
    uint4 o;
    o.x = f2tf32(v.x); o.y = f2tf32(v.y); o.z = f2tf32(v.z); o.w = f2tf32(v.w);
    ((uint4*)dst)[i] = o;
}

__global__ void router_k(const float* __restrict__ x, const float* __restrict__ gw) {
    __shared__ float s_gw[DIM * NEXP];
    for (int i = threadIdx.x; i < DIM * NEXP; i += blockDim.x) s_gw[i] = gw[i];
    __syncthreads();

    int t    = (int)((blockIdx.x * blockDim.x + threadIdx.x) >> 5);
    int lane = threadIdx.x & 31;
    if (t >= T_TOK) return;

    const float* xr = x + (size_t)t * DIM;
    float acc[NEXP];
#pragma unroll
    for (int e = 0; e < NEXP; e++) acc[e] = 0.f;
    for (int d = lane; d < DIM; d += 32) {
        float xv = xr[d];
#pragma unroll
        for (int e = 0; e < NEXP; e++) acc[e] = fmaf(xv, s_gw[d * NEXP + e], acc[e]);
    }
#pragma unroll
    for (int off = 16; off; off >>= 1) {
#pragma unroll
        for (int e = 0; e < NEXP; e++)
            acc[e] += __shfl_xor_sync(0xffffffffu, acc[e], off);
    }
    if (lane != 0) return;

    float mx = acc[0];
#pragma unroll
    for (int e = 1; e < NEXP; e++) mx = fmaxf(mx, acc[e]);
    float p[NEXP]; float s = 0.f;
#pragma unroll
    for (int e = 0; e < NEXP; e++) { p[e] = expf(acc[e] - mx); s += p[e]; }
    float inv = 1.f / s;
#pragma unroll
    for (int e = 0; e < NEXP; e++) { p[e] *= inv; atomicAdd(&g_probsum[e], p[e]); }

    int i0 = 0;
#pragma unroll
    for (int e = 1; e < NEXP; e++) if (p[e] > p[i0]) i0 = e;
    int i1 = (i0 == 0) ? 1 : 0;
#pragma unroll
    for (int e = 0; e < NEXP; e++) if (e != i0 && p[e] > p[i1]) i1 = e;

    float w0 = p[i0], w1 = p[i1];
    float ws = 1.f / (w0 + w1);
    w0 *= ws; w1 *= ws;

    int p0 = atomicAdd(&g_count[i0], 1);
    g_tok[i0 * MAXB + p0] = t;
    g_slot[t * 2 + 0]  = i0 * MAXB + p0;
    g_slotw[t * 2 + 0] = w0;
    int p1 = atomicAdd(&g_count[i1], 1);
    g_tok[i1 * MAXB + p1] = t;
    g_slot[t * 2 + 1]  = i1 * MAXB + p1;
    g_slotw[t * 2 + 1] = w1;
}

__global__ void finalize_k(float* __restrict__ loss_out) {
    int off = 0;
    for (int e = 0; e < NEXP; e++) { g_offset[e] = off; off += g_count[e]; }
    float s = 0.f;
    for (int e = 0; e < NEXP; e++) {
        float m = g_probsum[e] * (1.f / (float)T_TOK);
        s += m * m;
    }
    *loss_out = (float)NEXP * s;
}

// ---- async copy helpers ----
__device__ __forceinline__ void cp_async16(uint32_t saddr, const void* gptr) {
    asm volatile("cp.async.cg.shared.global [%0], [%1], 16;\n" :: "r"(saddr), "l"(gptr));
}
__device__ __forceinline__ void cp_commit() {
    asm volatile("cp.async.commit_group;\n" ::: "memory");
}
__device__ __forceinline__ void cp_wait1() {
    asm volatile("cp.async.wait_group 1;\n" ::: "memory");
}
__device__ __forceinline__ void mma_tf32(float c[4], uint32_t a0, uint32_t a1,
                                         uint32_t a2, uint32_t a3,
                                         uint32_t b0, uint32_t b1) {
    asm volatile(
        "mma.sync.aligned.m16n8k8.row.col.f32.tf32.tf32.f32 "
        "{%0,%1,%2,%3}, {%4,%5,%6,%7}, {%8,%9}, {%0,%1,%2,%3};\n"
        : "+f"(c[0]), "+f"(c[1]), "+f"(c[2]), "+f"(c[3])
        : "r"(a0), "r"(a1), "r"(a2), "r"(a3), "r"(b0), "r"(b1));
}

// One BK=32 slab: operands already tf32-rounded — raw bit loads, no cvt.
__device__ __forceinline__ void compute_slab(const uint32_t* __restrict__ As,
                                             const uint32_t* __restrict__ Bs,
                                             int wm, int wn, int lane,
                                             float acc[4][4][4]) {
#pragma unroll
    for (int ks = 0; ks < 4; ks++) {
        uint32_t af[4][4], bf[4][2];
        int c0 = ks * 8 + (lane & 3);
#pragma unroll
        for (int mt = 0; mt < 4; mt++) {
            int r = wm + mt * 16 + (lane >> 2);
            af[mt][0] = As[r * ASTRIDE + c0];
            af[mt][1] = As[(r + 8) * ASTRIDE + c0];
            af[mt][2] = As[r * ASTRIDE + c0 + 4];
            af[mt][3] = As[(r + 8) * ASTRIDE + c0 + 4];
        }
#pragma unroll
        for (int nt = 0; nt < 4; nt++) {
            int col = wn + nt * 8 + (lane >> 2);
            bf[nt][0] = Bs[c0 * BSTRIDE + col];
            bf[nt][1] = Bs[(c0 + 4) * BSTRIDE + col];
        }
#pragma unroll
        for (int mt = 0; mt < 4; mt++)
#pragma unroll
            for (int nt = 0; nt < 4; nt++)
                mma_tf32(acc[mt][nt], af[mt][0], af[mt][1], af[mt][2], af[mt][3],
                         bf[nt][0], bf[nt][1]);
    }
}

// GEMM1: hidden = round_tf32(gelu(gather(xr) @ w1r[e] + b1[e])).  K=512.
// grid: (n-tiles, m-tiles, expert) — n fastest for L2 A-slab reuse.
__global__ __launch_bounds__(256, 2) void ffn1_k(const float* __restrict__ b1) {
    const int e  = blockIdx.z;
    const int ne = g_count[e];
    const int m0 = blockIdx.y * BM;
    if (m0 >= ne) return;
    const int n0   = blockIdx.x * BN;
    const int base = g_offset[e];

    extern __shared__ float smem[];
    const int tid  = threadIdx.x;
    const int lane = tid & 31;
    const int warp = tid >> 5;
    const int wm   = (warp & 1) * 64;
    const int wn   = (warp >> 1) * 32;

    const float* srcA[4];
    uint32_t dstA[4];
#pragma unroll
    for (int l = 0; l < 4; l++) {
        int idx = tid + l * 256;
        int row = idx >> 3, ch = idx & 7;
        int tok = g_tok[e * MAXB + min(m0 + row, ne - 1)];
        srcA[l] = g_xr + (size_t)tok * DIM + ch * 4;
        dstA[l] = (uint32_t)(row * ASTRIDE + ch * 4) * 4u;
    }
    const float* srcB[4];
    uint32_t dstB[4];
    const float* Wb = g_w1r + (size_t)e * DIM * FDIM + n0;
#pragma unroll
    for (int l = 0; l < 4; l++) {
        int idx = tid + l * 256;
        int kr = idx >> 5, ch = idx & 31;
        srcB[l] = Wb + (size_t)kr * FDIM + ch * 4;
        dstB[l] = (uint32_t)(A_ELEMS + kr * BSTRIDE + ch * 4) * 4u;
    }
    uint32_t sbase = (uint32_t)__cvta_generic_to_shared(smem);

    auto load_stage = [&](int s, int k0) {
        uint32_t soff = sbase + (uint32_t)(s * STAGE_ELEMS * 4);
#pragma unroll
        for (int l = 0; l < 4; l++) cp_async16(soff + dstA[l], srcA[l] + k0);
#pragma unroll
        for (int l = 0; l < 4; l++) cp_async16(soff + dstB[l], srcB[l] + (size_t)k0 * FDIM);
    };

    float acc[4][4][4];
#pragma unroll
    for (int i = 0; i < 4; i++)
#pragma unroll
        for (int j = 0; j < 4; j++)
#pragma unroll
            for (int k = 0; k < 4; k++) acc[i][j][k] = 0.f;

    constexpr int KITERS = DIM / BK;  // 16
    load_stage(0, 0);
    cp_commit();
    for (int it = 0; it < KITERS; it++) {
        if (it + 1 < KITERS) load_stage((it + 1) & 1, (it + 1) * BK);
        cp_commit();
        cp_wait1();
        __syncthreads();
        const uint32_t* As = (const uint32_t*)(smem + (it & 1) * STAGE_ELEMS);
        compute_slab(As, As + A_ELEMS, wm, wn, lane, acc);
        __syncthreads();
    }

    // epilogue: bias + exact gelu in fp32, store tf32-rounded
#pragma unroll
    for (int nt = 0; nt < 4; nt++) {
        int c = n0 + wn + nt * 8 + 2 * (lane & 3);
        float2 bb = *(const float2*)(b1 + (size_t)e * FDIM + c);
#pragma unroll
        for (int mt = 0; mt < 4; mt++) {
            int r = wm + mt * 16 + (lane >> 2);
            int mrow0 = m0 + r, mrow1 = mrow0 + 8;
            if (mrow0 < ne) {
                float v0 = acc[mt][nt][0] + bb.x;
                float v1 = acc[mt][nt][1] + bb.y;
                uint2 o = { f2tf32(v0 * normcdff(v0)), f2tf32(v1 * normcdff(v1)) };
                *(uint2*)(g_hidden + (size_t)(base + mrow0) * FDIM + c) = o;
            }
            if (mrow1 < ne) {
                float v2 = acc[mt][nt][2] + bb.x;
                float v3 = acc[mt][nt][3] + bb.y;
                uint2 o = { f2tf32(v2 * normcdff(v2)), f2tf32(v3 * normcdff(v3)) };
                *(uint2*)(g_hidden + (size_t)(base + mrow1) * FDIM + c) = o;
            }
        }
    }
}

// GEMM2: out = hidden @ w2r[e] + b2[e].  K=2048, N=512.
__global__ __launch_bounds__(256, 2) void ffn2_k(const float* __restrict__ b2) {
    const int e  = blockIdx.z;
    const int ne = g_count[e];
    const int m0 = blockIdx.y * BM;
    if (m0 >= ne) return;
    const int n0   = blockIdx.x * BN;
    const int base = g_offset[e];

    extern __shared__ float smem[];
    const int tid  = threadIdx.x;
    const int lane = tid & 31;
    const int warp = tid >> 5;
    const int wm   = (warp & 1) * 64;
    const int wn   = (warp >> 1) * 32;

    const float* srcA[4];
    uint32_t dstA[4];
#pragma unroll
    for (int l = 0; l < 4; l++) {
        int idx = tid + l * 256;
        int row = idx >> 3, ch = idx & 7;
        int r = base + min(m0 + row, ne - 1);
        srcA[l] = g_hidden + (size_t)r * FDIM + ch * 4;
        dstA[l] = (uint32_t)(row * ASTRIDE + ch * 4) * 4u;
    }
    const float* srcB[4];
    uint32_t dstB[4];
    const float* Wb = g_w2r + (size_t)e * FDIM * DIM + n0;
#pragma unroll
    for (int l = 0; l < 4; l++) {
        int idx = tid + l * 256;
        int kr = idx >> 5, ch = idx & 31;
        srcB[l] = Wb + (size_t)kr * DIM + ch * 4;
        dstB[l] = (uint32_t)(A_ELEMS + kr * BSTRIDE + ch * 4) * 4u;
    }
    uint32_t sbase = (uint32_t)__cvta_generic_to_shared(smem);

    auto load_stage = [&](int s, int k0) {
        uint32_t soff = sbase + (uint32_t)(s * STAGE_ELEMS * 4);
#pragma unroll
        for (int l = 0; l < 4; l++) cp_async16(soff + dstA[l], srcA[l] + k0);
#pragma unroll
        for (int l = 0; l < 4; l++) cp_async16(soff + dstB[l], srcB[l] + (size_t)k0 * DIM);
    };

    float acc[4][4][4];
#pragma unroll
    for (int i = 0; i < 4; i++)
#pragma unroll
        for (int j = 0; j < 4; j++)
#pragma unroll
            for (int k = 0; k < 4; k++) acc[i][j][k] = 0.f;

    constexpr int KITERS = FDIM / BK;  // 64
    load_stage(0, 0);
    cp_commit();
    for (int it = 0; it < KITERS; it++) {
        if (it + 1 < KITERS) load_stage((it + 1) & 1, (it + 1) * BK);
        cp_commit();
        cp_wait1();
        __syncthreads();
        const uint32_t* As = (const uint32_t*)(smem + (it & 1) * STAGE_ELEMS);
        compute_slab(As, As + A_ELEMS, wm, wn, lane, acc);
        __syncthreads();
    }

#pragma unroll
    for (int nt = 0; nt < 4; nt++) {
        int c = n0 + wn + nt * 8 + 2 * (lane & 3);
        float2 bb = *(const float2*)(b2 + (size_t)e * DIM + c);
#pragma unroll
        for (int mt = 0; mt < 4; mt++) {
            int r = wm + mt * 16 + (lane >> 2);
            int mrow0 = m0 + r, mrow1 = mrow0 + 8;
            if (mrow0 < ne) {
                float2 o = { acc[mt][nt][0] + bb.x, acc[mt][nt][1] + bb.y };
                *(float2*)(g_oscr + (size_t)(base + mrow0) * DIM + c) = o;
            }
            if (mrow1 < ne) {
                float2 o = { acc[mt][nt][2] + bb.x, acc[mt][nt][3] + bb.y };
                *(float2*)(g_oscr + (size_t)(base + mrow1) * DIM + c) = o;
            }
        }
    }
}

__global__ void combine_k(float* __restrict__ y) {
    int gid = blockIdx.x * blockDim.x + threadIdx.x;
    if (gid >= T_TOK * (DIM / 4)) return;
    int t = gid >> 7;
    int q = (gid & 127) * 4;
    int s0 = g_slot[t * 2 + 0], s1 = g_slot[t * 2 + 1];
    float w0 = g_slotw[t * 2 + 0], w1 = g_slotw[t * 2 + 1];
    int r0 = g_offset[s0 >> 13] + (s0 & (MAXB - 1));
    int r1 = g_offset[s1 >> 13] + (s1 & (MAXB - 1));
    float4 a = *(const float4*)(g_oscr + (size_t)r0 * DIM + q);
    float4 b = *(const float4*)(g_oscr + (size_t)r1 * DIM + q);
    float4 o;
    o.x = w0 * a.x + w1 * b.x;
    o.y = w0 * a.y + w1 * b.y;
    o.z = w0 * a.z + w1 * b.z;
    o.w = w0 * a.w + w1 * b.w;
    *(float4*)(y + (size_t)t * DIM + q) = o;
}

}  // namespace

extern "C" void kernel_launch(void* const* d_in, const int* in_sizes, int n_in,
                              void* d_out, int out_size) {
    const float* x  = (const float*)d_in[0];
    const float* gw = (const float*)d_in[1];
    const float* w1 = (const float*)d_in[2];
    const float* b1 = (const float*)d_in[3];
    const float* w2 = (const float*)d_in[4];
    const float* b2 = (const float*)d_in[5];
    float* y    = (float*)d_out;
    float* loss = y + (out_size - 1);

    static bool attr_done = false;
    if (!attr_done) {
        cudaFuncSetAttribute(ffn1_k, cudaFuncAttributeMaxDynamicSharedMemorySize, SMEM_BYTES);
        cudaFuncSetAttribute(ffn2_k, cudaFuncAttributeMaxDynamicSharedMemorySize, SMEM_BYTES);
        attr_done = true;
    }

    float* xr_p;  cudaGetSymbolAddress((void**)&xr_p, g_xr);
    float* w1r_p; cudaGetSymbolAddress((void**)&w1r_p, g_w1r);
    float* w2r_p; cudaGetSymbolAddress((void**)&w2r_p, g_w2r);

    init_k<<<1, 32>>>();
    router_k<<<(T_TOK * 32 + 255) / 256, 256>>>(x, gw);
    finalize_k<<<1, 1>>>(loss);

    constexpr int XN4  = T_TOK * DIM / 4;
    constexpr int W1N4 = NEXP * DIM * FDIM / 4;
    constexpr int W2N4 = NEXP * FDIM * DIM / 4;
    round_k<<<(XN4 + 255) / 256, 256>>>(x, xr_p, XN4);
    round_k<<<(W1N4 + 255) / 256, 256>>>(w1, w1r_p, W1N4);
    round_k<<<(W2N4 + 255) / 256, 256>>>(w2, w2r_p, W2N4);

    ffn1_k<<<dim3(FDIM / BN, T_TOK / BM, NEXP), 256, SMEM_BYTES>>>(b1);
    ffn2_k<<<dim3(DIM / BN, T_TOK / BM, NEXP), 256, SMEM_BYTES>>>(b2);
    combine_k<<<(T_TOK * (DIM / 4) + 255) / 256, 256>>>(y);
}